// round 9
// baseline (speedup 1.0000x reference)
#include <cuda_runtime.h>
#include <cstdint>

// Problem constants
#define B_    256
#define T_    2048
#define F_    64
#define H_    512
#define C_    128

// Partitioning: 32 j-chunks (16 h-units) x 4 batch-chunks (64 batches) = 128 CTAs
#define NJ    32
#define NCTA  128
#define NTHR  512
#define JT    16      // h-units per CTA (=> 64 gate rows)
#define BT    64      // batches per CTA

#define WS_STR  68    // weight row stride (floats): 64 used + 4 pad, 16B-aligned rows
#define PAN_STR 68    // panel row stride (floats)
#define PANBUF  (64 * PAN_STR)
#define HN_STR  68

// ---------------- device globals (static scratch; zero-initialized at load) --
__device__ float g_hT[2][H_][B_];            // transposed h state, double buffered
__device__ float g_part[2][NJ][B_][C_];      // decoder partial logits, parity buffered
__device__ unsigned int g_count = 0;
__device__ volatile unsigned int g_sense = 0;

__device__ __forceinline__ float sigm(float x) { return 1.0f / (1.0f + expf(-x)); }

// SMEM layout (floats)
#define OFF_WS    0
#define OFF_PAN   (OFF_WS   + 576 * WS_STR)          // 39168
#define OFF_HN    (OFF_PAN  + 2 * PANBUF)            // 39168 + 8704 = 47872
#define OFF_WD    (OFF_HN   + JT * HN_STR)           // 48960
#define OFF_BSUM  (OFF_WD   + JT * C_)               // 51008
#define OFF_BD    (OFF_BSUM + 64)                    // 51072
#define OFF_RED   (OFF_BD   + C_)                    // 51200
#define SMEM_FLOATS (OFF_RED + 16)                   // 51216
#define SMEM_BYTES  (SMEM_FLOATS * 4)                // 204,864 B

__global__ void __launch_bounds__(NTHR, 1) lstm_persist_kernel(
    const float* __restrict__ X,    // [B, T, F]
    const float* __restrict__ Wih,  // [4H, F]
    const float* __restrict__ Whh,  // [4H, H]
    const float* __restrict__ bih,  // [4H]
    const float* __restrict__ bhh,  // [4H]
    const float* __restrict__ Wd,   // [C, H]
    const float* __restrict__ bd,   // [C]
    float* __restrict__ out)        // [B, T*C]
{
    extern __shared__ float sm[];
    float* ws   = sm + OFF_WS;    // [576][WS_STR]  row r = jj*4 + gate (i,f,g,o)
    float* hn   = sm + OFF_HN;    // [16][HN_STR]   h_new staging [jj][b]
    float* wd   = sm + OFF_WD;    // [16][128]      W_d slice [jj][c]
    float* bsum = sm + OFF_BSUM;  // [64]
    float* bds  = sm + OFF_BD;    // [128]
    float* red  = sm + OFF_RED;   // [16]

    const int tid  = threadIdx.x;
    const int cta  = blockIdx.x;
    const int jb   = cta & 31;        // h-chunk id
    const int bb   = cta >> 5;        // batch-chunk id
    const int J0   = jb * JT;
    const int b0   = bb * BT;
    const int tx   = tid & 15;        // jj index (4 gate rows)
    const int ty   = tid >> 4;        // batch pair index (0..31)
    const int wrp  = tid >> 5;        // warp id (0..15)
    const int lane = tid & 31;
    const int q8   = tid >> 6;        // 0..7  (x staging: 8 k's)
    const int bl   = tid & 63;        // 0..63 (x staging / decoder batch)

    // ---- one-time SMEM init: weights + biases (stationary for whole launch) ----
    for (int idx = tid; idx < 576 * 64; idx += NTHR) {
        int k = idx >> 6, r = idx & 63;
        int jj = r >> 2, g = r & 3;
        int grow = g * H_ + J0 + jj;             // PyTorch gate order i,f,g,o
        float v = (k < F_) ? Wih[(size_t)grow * F_ + k]
                           : Whh[(size_t)grow * H_ + (k - F_)];
        ws[k * WS_STR + r] = v;
    }
    for (int idx = tid; idx < JT * C_; idx += NTHR) {
        int jj = idx >> 7, c = idx & 127;
        wd[jj * C_ + c] = Wd[(size_t)c * H_ + J0 + jj];
    }
    if (tid < 64) {
        int jj = tid >> 2, g = tid & 3;
        bsum[tid] = bih[g * H_ + J0 + jj] + bhh[g * H_ + J0 + jj];
    }
    if (tid < C_) bds[tid] = bd[tid];

    float creg[2] = {0.f, 0.f};     // cell state: jj=tx, batches ty*2, ty*2+1
    float4 xr0, xr1;                // next-step x prefetch (8 floats)
    float2 hr[4];                   // next h-panel prefetch (4 rows/warp)

    // ---- pre-loop: stage x(t=0) into pan buffer 0; prefetch h panel 1 ----
    {
        const float* xp = X + ((size_t)(b0 + bl) * T_) * F_ + q8 * 8;
        float4 xa = *(const float4*)xp;
        float4 xb = *(const float4*)(xp + 4);
        float* p0 = sm + OFF_PAN;
        p0[(q8 * 8 + 0) * PAN_STR + bl] = xa.x;
        p0[(q8 * 8 + 1) * PAN_STR + bl] = xa.y;
        p0[(q8 * 8 + 2) * PAN_STR + bl] = xa.z;
        p0[(q8 * 8 + 3) * PAN_STR + bl] = xa.w;
        p0[(q8 * 8 + 4) * PAN_STR + bl] = xb.x;
        p0[(q8 * 8 + 5) * PAN_STR + bl] = xb.y;
        p0[(q8 * 8 + 6) * PAN_STR + bl] = xb.z;
        p0[(q8 * 8 + 7) * PAN_STR + bl] = xb.w;
        #pragma unroll
        for (int i = 0; i < 4; ++i)
            hr[i] = __ldcg((const float2*)&g_hT[0][wrp * 4 + i][b0 + lane * 2]);
    }
    int cur = 0;
    __syncthreads();

    for (int t = 0; t < T_; ++t) {
        const int par = t & 1;

        float acc[4][2];
        #pragma unroll
        for (int g = 0; g < 4; ++g) { acc[g][0] = 0.f; acc[g][1] = 0.f; }

        // ---- gates GEMM: 9 K-panels of 64 (panel 0 = x, 1..8 = h) ----
        #pragma unroll 1
        for (int p = 0; p < 9; ++p) {
            float* pcur = sm + OFF_PAN + cur * PANBUF;
            float* pnxt = sm + OFF_PAN + (cur ^ 1) * PANBUF;

            if (p < 8) {
                // store prefetched h panel p+1 into the other buffer
                #pragma unroll
                for (int i = 0; i < 4; ++i) {
                    int r = wrp * 4 + i;
                    *(float2*)(pnxt + r * PAN_STR + lane * 2) = hr[i];
                }
                // prefetch h panel p+2 (rows (p+1)*64 ..)
                if (p <= 6) {
                    #pragma unroll
                    for (int i = 0; i < 4; ++i) {
                        int r = wrp * 4 + i;
                        hr[i] = __ldcg((const float2*)&g_hT[par][(p + 1) * 64 + r][b0 + lane * 2]);
                    }
                }
                // prefetch next step's x early (read-only, plenty of cover)
                if (p == 0 && t + 1 < T_) {
                    const float* xp2 = X + ((size_t)(b0 + bl) * T_ + (t + 1)) * F_ + q8 * 8;
                    xr0 = *(const float4*)xp2;
                    xr1 = *(const float4*)(xp2 + 4);
                }
            } else if (t + 1 < T_) {
                // p == 8: stage next step's x (panel 0) into the other buffer
                pnxt[(q8 * 8 + 0) * PAN_STR + bl] = xr0.x;
                pnxt[(q8 * 8 + 1) * PAN_STR + bl] = xr0.y;
                pnxt[(q8 * 8 + 2) * PAN_STR + bl] = xr0.z;
                pnxt[(q8 * 8 + 3) * PAN_STR + bl] = xr0.w;
                pnxt[(q8 * 8 + 4) * PAN_STR + bl] = xr1.x;
                pnxt[(q8 * 8 + 5) * PAN_STR + bl] = xr1.y;
                pnxt[(q8 * 8 + 6) * PAN_STR + bl] = xr1.z;
                pnxt[(q8 * 8 + 7) * PAN_STR + bl] = xr1.w;
            }

            // ---- compute panel p ----
            const float* wrow = ws + (p * 64) * WS_STR + tx * 4;
            const float* prow = pcur + ty * 2;
            #pragma unroll 8
            for (int kk = 0; kk < 64; ++kk) {
                float4 wv = *(const float4*)wrow;
                float2 hv = *(const float2*)prow;
                acc[0][0] += wv.x * hv.x; acc[0][1] += wv.x * hv.y;
                acc[1][0] += wv.y * hv.x; acc[1][1] += wv.y * hv.y;
                acc[2][0] += wv.z * hv.x; acc[2][1] += wv.z * hv.y;
                acc[3][0] += wv.w * hv.x; acc[3][1] += wv.w * hv.y;
                wrow += WS_STR;
                prow += PAN_STR;
            }
            __syncthreads();    // pnxt fully written AND pcur fully read
            cur ^= 1;
        }

        // ---- cell update (c stays in registers; 2 batches/thread) ----
        {
            float b_i = bsum[tx * 4 + 0], b_f = bsum[tx * 4 + 1];
            float b_g = bsum[tx * 4 + 2], b_o = bsum[tx * 4 + 3];
            #pragma unroll
            for (int bq = 0; bq < 2; ++bq) {
                float pi = acc[0][bq] + b_i;
                float pf = acc[1][bq] + b_f;
                float pg = acc[2][bq] + b_g;
                float po = acc[3][bq] + b_o;
                float iv = sigm(pi), fv = sigm(pf), gv = tanhf(pg), ov = sigm(po);
                float cn = fv * creg[bq] + iv * gv;
                creg[bq] = cn;
                hn[tx * HN_STR + ty * 2 + bq] = ov * tanhf(cn);
            }
        }
        __syncthreads();

        // ---- write h_new to global (next parity buffer), coalesced ----
        {
            int row = tid >> 5;           // 0..15
            float2 v = *(const float2*)(hn + row * HN_STR + lane * 2);
            *(float2*)(&g_hT[par ^ 1][J0 + row][b0 + lane * 2]) = v;
        }

        // ---- decoder partial logits from LOCAL h_new slice (relu fused) ----
        {
            float accd[16];
            #pragma unroll
            for (int i = 0; i < 16; ++i) accd[i] = 0.f;
            #pragma unroll
            for (int kk = 0; kk < JT; ++kk) {
                float hv = fmaxf(hn[kk * HN_STR + bl], 0.f);
                const float4* wp = (const float4*)(wd + kk * C_ + q8 * 16);
                #pragma unroll
                for (int j = 0; j < 4; ++j) {
                    float4 w = wp[j];
                    accd[4 * j + 0] += w.x * hv; accd[4 * j + 1] += w.y * hv;
                    accd[4 * j + 2] += w.z * hv; accd[4 * j + 3] += w.w * hv;
                }
            }
            float4* dst = (float4*)(&g_part[par][jb][b0 + bl][q8 * 16]);
            #pragma unroll
            for (int j = 0; j < 4; ++j)
                dst[j] = make_float4(accd[4 * j + 0], accd[4 * j + 1],
                                     accd[4 * j + 2], accd[4 * j + 3]);
        }

        // ---- grid-wide sync (sense-reversing; 2048/launch -> state resets) ----
        {
            unsigned target = (unsigned)((t & 1) ^ 1);
            __syncthreads();
            if (tid == 0) {
                __threadfence();                      // publish hT + partials to L2
                unsigned v = atomicAdd(&g_count, 1u);
                if (v == NCTA - 1) {
                    g_count = 0;
                    __threadfence();
                    g_sense = target;
                } else {
                    while (g_sense != target) { __nanosleep(64); }
                }
                __threadfence();
            }
            __syncthreads();
        }

        // ---- prefetch next step's h panel 1 (now that hT[par^1] is complete) ----
        if (t + 1 < T_) {
            #pragma unroll
            for (int i = 0; i < 4; ++i)
                hr[i] = __ldcg((const float2*)&g_hT[par ^ 1][wrp * 4 + i][b0 + lane * 2]);
        }

        // ---- phase 4: reduce partials + softmax + write out (2 batches/CTA) ----
        {
            const bool act = tid < 256;
            int half = (tid >> 7) & 1;
            int c    = tid & 127;
            int b    = cta * 2 + half;
            float v = 0.f, e = 0.f;
            if (act) {
                v = bds[c];
                #pragma unroll
                for (int j2 = 0; j2 < NJ; ++j2)
                    v += __ldcg(&g_part[par][j2][b][c]);
                float m = v;
                #pragma unroll
                for (int o = 16; o; o >>= 1)
                    m = fmaxf(m, __shfl_xor_sync(0xffffffffu, m, o));
                if (lane == 0) red[wrp] = m;          // warps 0..7
            }
            __syncthreads();
            if (act) {
                float gm = fmaxf(fmaxf(red[half * 4 + 0], red[half * 4 + 1]),
                                 fmaxf(red[half * 4 + 2], red[half * 4 + 3]));
                e = expf(v - gm);
                float s = e;
                #pragma unroll
                for (int o = 16; o; o >>= 1)
                    s += __shfl_xor_sync(0xffffffffu, s, o);
                if (lane == 0) red[8 + wrp] = s;
            }
            __syncthreads();
            if (act) {
                float gs = red[8 + half * 4 + 0] + red[8 + half * 4 + 1] +
                           red[8 + half * 4 + 2] + red[8 + half * 4 + 3];
                out[(size_t)b * (T_ * C_) + (size_t)t * C_ + c] = e / gs;
            }
        }
        __syncthreads();
    }

    // ---- restore g_hT[0] to zeros so every launch/replay is identical ----
    {
        int row = tid >> 5;
        *(float2*)(&g_hT[0][J0 + row][b0 + lane * 2]) = make_float2(0.f, 0.f);
    }
}

extern "C" void kernel_launch(void* const* d_in, const int* in_sizes, int n_in,
                              void* d_out, int out_size) {
    (void)in_sizes; (void)n_in; (void)out_size;
    const float* x   = (const float*)d_in[0];
    const float* Wih = (const float*)d_in[1];
    const float* Whh = (const float*)d_in[2];
    const float* bih = (const float*)d_in[3];
    const float* bhh = (const float*)d_in[4];
    const float* Wd  = (const float*)d_in[5];
    const float* bd  = (const float*)d_in[6];
    float* out = (float*)d_out;

    cudaFuncSetAttribute(lstm_persist_kernel,
                         cudaFuncAttributeMaxDynamicSharedMemorySize, SMEM_BYTES);
    lstm_persist_kernel<<<NCTA, NTHR, SMEM_BYTES>>>(x, Wih, Whh, bih, bhh, Wd, bd, out);
}

// round 12
// speedup vs baseline: 1.4019x; 1.4019x over previous
#include <cuda_runtime.h>
#include <cuda_bf16.h>
#include <cstdint>

// Problem constants
#define B_    256
#define T_    2048
#define F_    64
#define H_    512
#define C_    128

// Partitioning: 64 gate-row chunks (32 rows = 8 h-units) x 2 batch chunks (128) = 128 CTAs
#define NJ    64
#define NCTA  128
#define NTHR  256
#define JTH   8       // h-units per CTA
#define NROW  32      // gate rows per CTA
#define MB    128     // batches per CTA

#define ASTR  144     // A panel row stride bytes (72 bf16)
#define AHALF 18432   // 128 rows * 144 B (one hi or lo plane)
#define ABUF  36864   // hi + lo

// SMEM byte offsets
#define OFF_A     0                       // 2 x ABUF = 73728
#define OFF_WF    73728                   // weight frags: 36*4*32*16 = 73728
#define OFF_WD    (OFF_WF + 73728)        // 147456 : 8x128 f32
#define OFF_HN    (OFF_WD + 4096)         // 151552 : 8x128 f32
#define OFF_BSUM  (OFF_HN + 4096)         // 155648 : 32 f32
#define OFF_BD    (OFF_BSUM + 128)        // 155776 : 128 f32
#define OFF_RED   (OFF_BD + 512)          // 156288 : 16 f32
#define SMEM_BYTES (OFF_RED + 64)         // 156352

// ---------------- device globals (static scratch; zero-initialized) ---------
__device__ __nv_bfloat16 g_hhi[2][B_][H_];   // h hi, double buffered
__device__ __nv_bfloat16 g_hlo[2][B_][H_];   // h lo
__device__ float g_part[2][NJ][B_][C_];      // decoder partial logits
__device__ unsigned int g_count = 0;
__device__ volatile unsigned int g_sense = 0;

__device__ __forceinline__ float sigm(float x) { return 1.0f / (1.0f + expf(-x)); }

__device__ __forceinline__ void pack_hilo(float f0, float f1, uint32_t& hi, uint32_t& lo) {
    __nv_bfloat16 h0 = __float2bfloat16(f0), h1 = __float2bfloat16(f1);
    float r0 = f0 - __bfloat162float(h0), r1 = f1 - __bfloat162float(h1);
    __nv_bfloat16 l0 = __float2bfloat16(r0), l1 = __float2bfloat16(r1);
    hi = (uint32_t)__bfloat16_as_ushort(h0) | ((uint32_t)__bfloat16_as_ushort(h1) << 16);
    lo = (uint32_t)__bfloat16_as_ushort(l0) | ((uint32_t)__bfloat16_as_ushort(l1) << 16);
}

#define LDMX4(r0,r1,r2,r3,addr) \
    asm volatile("ldmatrix.sync.aligned.m8n8.x4.shared.b16 {%0,%1,%2,%3}, [%4];" \
                 : "=r"(r0),"=r"(r1),"=r"(r2),"=r"(r3) : "r"(addr))

#define MMA16816(d,a0,a1,a2,a3,b0,b1) \
    asm volatile("mma.sync.aligned.m16n8k16.row.col.f32.bf16.bf16.f32 " \
                 "{%0,%1,%2,%3}, {%4,%5,%6,%7}, {%8,%9}, {%0,%1,%2,%3};" \
                 : "+f"(d[0]),"+f"(d[1]),"+f"(d[2]),"+f"(d[3]) \
                 : "r"(a0),"r"(a1),"r"(a2),"r"(a3), "r"(b0),"r"(b1))

__global__ void __launch_bounds__(NTHR, 1) lstm_hmma_kernel(
    const float* __restrict__ X,    // [B, T, F]
    const float* __restrict__ Wih,  // [4H, F]
    const float* __restrict__ Whh,  // [4H, H]
    const float* __restrict__ bih,  // [4H]
    const float* __restrict__ bhh,  // [4H]
    const float* __restrict__ Wd,   // [C, H]
    const float* __restrict__ bd,   // [C]
    float* __restrict__ out)        // [B, T*C]
{
    extern __shared__ char smc[];
    const uint32_t smb = (uint32_t)__cvta_generic_to_shared(smc);
    uint4*  wfrag = (uint4*)(smc + OFF_WF);   // [36][4][32] {bhi0,bhi1,blo0,blo1}
    float*  wd    = (float*)(smc + OFF_WD);   // [8][128]
    float*  hn    = (float*)(smc + OFF_HN);   // [8][128]
    float*  bsum  = (float*)(smc + OFF_BSUM); // [32]
    float*  bds   = (float*)(smc + OFF_BD);   // [128]
    float*  red   = (float*)(smc + OFF_RED);  // [16]

    const int tid  = threadIdx.x;
    const int cta  = blockIdx.x;
    const int jb   = cta >> 1;           // gate-row chunk 0..63
    const int bb   = cta & 1;            // batch chunk 0..1
    const int J0h  = jb * JTH;
    const int b0   = bb * MB;
    const int wrp  = tid >> 5;           // warp id 0..7 = m-tile
    const int lane = tid & 31;
    const int row2 = tid >> 1;           // staging batch row 0..127
    const int seg  = tid & 1;            // staging k half

    // ---- one-time init: weight fragments (bf16 hi/lo, mma fragment order) ----
    for (int idx = tid; idx < 36 * 4 * 32; idx += NTHR) {
        int ks = idx >> 7, rem = idx & 127;
        int nt = rem >> 5, l = rem & 31;
        int n = nt * 8 + (l >> 2);                 // gate row 0..31
        int jj = n >> 2, g = n & 3;
        int grow = g * H_ + J0h + jj;              // PyTorch gate order i,f,g,o
        int kA = ks * 16 + (l & 3) * 2;            // rows kA,kA+1,kA+8,kA+9
        float w[4];
        #pragma unroll
        for (int e = 0; e < 4; ++e) {
            int k = kA + (e & 1) + (e >> 1) * 8;
            w[e] = (k < F_) ? Wih[(size_t)grow * F_ + k]
                            : Whh[(size_t)grow * H_ + (k - F_)];
        }
        uint32_t h0, l0, h1, l1;
        pack_hilo(w[0], w[1], h0, l0);
        pack_hilo(w[2], w[3], h1, l1);
        wfrag[idx] = make_uint4(h0, h1, l0, l1);
    }
    for (int idx = tid; idx < JTH * C_; idx += NTHR) {
        int kk = idx >> 7, c = idx & 127;
        wd[kk * C_ + c] = Wd[(size_t)c * H_ + J0h + kk];
    }
    if (tid < NROW) {
        int jj = tid >> 2, g = tid & 3;
        bsum[tid] = bih[g * H_ + J0h + jj] + bhh[g * H_ + J0h + jj];
    }
    if (tid < C_) bds[tid] = bd[tid];
    __syncthreads();

    // bias registers for this thread's 4 jj values
    const int jbit = (lane >> 1) & 1;
    float bi[4], bf[4], bg[4], bo[4];
    #pragma unroll
    for (int nt = 0; nt < 4; ++nt) {
        int jj = 2 * nt + jbit;
        bi[nt] = bsum[jj * 4 + 0]; bf[nt] = bsum[jj * 4 + 1];
        bg[nt] = bsum[jj * 4 + 2]; bo[nt] = bsum[jj * 4 + 3];
    }

    float cst[4] = {0.f, 0.f, 0.f, 0.f};   // cell state: 4 jj x 1 batch
    const int mloc = (wrp << 4) + (lane >> 2) + ((lane & 1) << 3);

    uint4 hrh[4], hrl[4];                  // h-panel prefetch
    float4 xr[8];                          // next-step x prefetch

    // ---- preloop: stage x(t=0) into buf0; prefetch h panel 1 ----
    {
        const float* xp = X + ((size_t)(b0 + row2) * T_) * F_ + seg * 32;
        char* a = smc + OFF_A + row2 * ASTR + seg * 64;
        #pragma unroll
        for (int i = 0; i < 4; ++i) {
            float4 va = *(const float4*)(xp + i * 8);
            float4 vb = *(const float4*)(xp + i * 8 + 4);
            uint32_t h0,l0,h1,l1,h2,l2,h3,l3;
            pack_hilo(va.x, va.y, h0, l0); pack_hilo(va.z, va.w, h1, l1);
            pack_hilo(vb.x, vb.y, h2, l2); pack_hilo(vb.z, vb.w, h3, l3);
            *(uint4*)(a + i * 16)         = make_uint4(h0, h1, h2, h3);
            *(uint4*)(a + AHALF + i * 16) = make_uint4(l0, l1, l2, l3);
        }
        #pragma unroll
        for (int j = 0; j < 4; ++j) {
            hrh[j] = __ldcg((const uint4*)&g_hhi[0][b0 + row2][seg * 32 + j * 8]);
            hrl[j] = __ldcg((const uint4*)&g_hlo[0][b0 + row2][seg * 32 + j * 8]);
        }
    }
    int cur = 0;
    __syncthreads();

    for (int t = 0; t < T_; ++t) {
        const int par = t & 1;

        float acc[4][4];
        #pragma unroll
        for (int nt = 0; nt < 4; ++nt)
            #pragma unroll
            for (int i = 0; i < 4; ++i) acc[nt][i] = 0.f;

        // ---- gates GEMM: 9 panels of K=64 ----
        #pragma unroll 1
        for (int p = 0; p < 9; ++p) {
            const uint32_t abase = smb + OFF_A + (cur ^ 1) * ABUF;   // nxt
            // stage next panel into nxt
            if (p < 8) {
                char* a = smc + OFF_A + (cur ^ 1) * ABUF + row2 * ASTR + seg * 64;
                #pragma unroll
                for (int j = 0; j < 4; ++j) {
                    *(uint4*)(a + j * 16)         = hrh[j];
                    *(uint4*)(a + AHALF + j * 16) = hrl[j];
                }
                if (p <= 6) {
                    int kb = (p + 1) * 64 + seg * 32;
                    #pragma unroll
                    for (int j = 0; j < 4; ++j) {
                        hrh[j] = __ldcg((const uint4*)&g_hhi[par][b0 + row2][kb + j * 8]);
                        hrl[j] = __ldcg((const uint4*)&g_hlo[par][b0 + row2][kb + j * 8]);
                    }
                }
                if (p == 7 && t + 1 < T_) {
                    const float* xp = X + ((size_t)(b0 + row2) * T_ + (t + 1)) * F_ + seg * 32;
                    #pragma unroll
                    for (int i = 0; i < 4; ++i) {
                        xr[2 * i]     = *(const float4*)(xp + i * 8);
                        xr[2 * i + 1] = *(const float4*)(xp + i * 8 + 4);
                    }
                }
            } else if (t + 1 < T_) {
                char* a = smc + OFF_A + (cur ^ 1) * ABUF + row2 * ASTR + seg * 64;
                #pragma unroll
                for (int i = 0; i < 4; ++i) {
                    float4 va = xr[2 * i], vb = xr[2 * i + 1];
                    uint32_t h0,l0,h1,l1,h2,l2,h3,l3;
                    pack_hilo(va.x, va.y, h0, l0); pack_hilo(va.z, va.w, h1, l1);
                    pack_hilo(vb.x, vb.y, h2, l2); pack_hilo(vb.z, vb.w, h3, l3);
                    *(uint4*)(a + i * 16)         = make_uint4(h0, h1, h2, h3);
                    *(uint4*)(a + AHALF + i * 16) = make_uint4(l0, l1, l2, l3);
                }
            }

            // compute panel p from cur
            const uint32_t ab = smb + OFF_A + cur * ABUF
                              + (wrp * 16 + (lane & 15)) * ASTR + (lane >> 4) * 16;
            #pragma unroll
            for (int ks = 0; ks < 4; ++ks) {
                uint32_t ah0, ah1, ah2, ah3, al0, al1, al2, al3;
                LDMX4(ah0, ah1, ah2, ah3, ab + ks * 32);
                LDMX4(al0, al1, al2, al3, ab + AHALF + ks * 32);
                const uint4* wf = &wfrag[((p * 4 + ks) * 4) * 32 + lane];
                #pragma unroll
                for (int nt = 0; nt < 4; ++nt) {
                    uint4 b = wf[nt * 32];
                    MMA16816(acc[nt], ah0, ah1, ah2, ah3, b.x, b.y);
                    MMA16816(acc[nt], al0, al1, al2, al3, b.x, b.y);
                    MMA16816(acc[nt], ah0, ah1, ah2, ah3, b.z, b.w);
                }
            }
            __syncthreads();   // cur fully read, nxt fully written
            cur ^= 1;
        }

        // ---- cell update: reassemble quads via lane-pair shuffles ----
        {
            const int odd = lane & 1;
            #pragma unroll
            for (int nt = 0; nt < 4; ++nt) {
                float t0 = __shfl_xor_sync(0xffffffffu, acc[nt][0], 1);
                float t1 = __shfl_xor_sync(0xffffffffu, acc[nt][1], 1);
                float t2 = __shfl_xor_sync(0xffffffffu, acc[nt][2], 1);
                float t3 = __shfl_xor_sync(0xffffffffu, acc[nt][3], 1);
                float pi = odd ? t2 : acc[nt][0];
                float pf = odd ? t3 : acc[nt][1];
                float pg = odd ? acc[nt][2] : t0;
                float po = odd ? acc[nt][3] : t1;
                pi += bi[nt]; pf += bf[nt]; pg += bg[nt]; po += bo[nt];
                float iv = sigm(pi), fv = sigm(pf), gv = tanhf(pg), ov = sigm(po);
                float cn = fv * cst[nt] + iv * gv;
                cst[nt] = cn;
                float hv = ov * tanhf(cn);
                hn[(2 * nt + jbit) * MB + mloc] = hv;
            }
        }
        __syncthreads();

        // ---- write h hi/lo to global (next parity), coalesced ----
        if (tid < MB) {
            uint32_t ph[4], pl[4];
            #pragma unroll
            for (int j = 0; j < 4; ++j)
                pack_hilo(hn[(2 * j) * MB + tid], hn[(2 * j + 1) * MB + tid],
                          ph[j], pl[j]);
            *(uint4*)&g_hhi[par ^ 1][b0 + tid][J0h] = make_uint4(ph[0], ph[1], ph[2], ph[3]);
            *(uint4*)&g_hlo[par ^ 1][b0 + tid][J0h] = make_uint4(pl[0], pl[1], pl[2], pl[3]);
        }

        // ---- decoder partial logits from local h slice (relu fused) ----
        {
            const int b_l = tid & 127, ch = tid >> 7;
            #pragma unroll
            for (int blk = 0; blk < 4; ++blk) {
                int cb = ch * 64 + blk * 16;
                float accd[16];
                #pragma unroll
                for (int i = 0; i < 16; ++i) accd[i] = 0.f;
                #pragma unroll
                for (int kk = 0; kk < JTH; ++kk) {
                    float hvv = fmaxf(hn[kk * MB + b_l], 0.f);
                    const float4* wp = (const float4*)(wd + kk * C_ + cb);
                    #pragma unroll
                    for (int j = 0; j < 4; ++j) {
                        float4 w = wp[j];
                        accd[4 * j + 0] += w.x * hvv; accd[4 * j + 1] += w.y * hvv;
                        accd[4 * j + 2] += w.z * hvv; accd[4 * j + 3] += w.w * hvv;
                    }
                }
                float4* dst = (float4*)(&g_part[par][jb][b0 + b_l][cb]);
                #pragma unroll
                for (int j = 0; j < 4; ++j)
                    dst[j] = make_float4(accd[4 * j], accd[4 * j + 1],
                                         accd[4 * j + 2], accd[4 * j + 3]);
            }
        }

        // ---- grid-wide sync (sense-reversing; even count -> state resets) ----
        {
            unsigned target = (unsigned)((t & 1) ^ 1);
            __syncthreads();
            if (tid == 0) {
                __threadfence();
                unsigned v = atomicAdd(&g_count, 1u);
                if (v == NCTA - 1) {
                    g_count = 0;
                    __threadfence();
                    g_sense = target;
                } else {
                    while (g_sense != target) { __nanosleep(64); }
                }
                __threadfence();
            }
            __syncthreads();
        }

        // ---- prefetch next step's h panel 1 ----
        if (t + 1 < T_) {
            #pragma unroll
            for (int j = 0; j < 4; ++j) {
                hrh[j] = __ldcg((const uint4*)&g_hhi[par ^ 1][b0 + row2][seg * 32 + j * 8]);
                hrl[j] = __ldcg((const uint4*)&g_hlo[par ^ 1][b0 + row2][seg * 32 + j * 8]);
            }
        }

        // ---- phase 4: reduce partials + softmax + write out (2 batches/CTA) ----
        {
            const int half = tid >> 7, c = tid & 127;
            const int b = cta * 2 + half;
            float v = bds[c];
            #pragma unroll 8
            for (int j2 = 0; j2 < NJ; ++j2)
                v += __ldcg(&g_part[par][j2][b][c]);
            float m = v;
            #pragma unroll
            for (int o = 16; o; o >>= 1)
                m = fmaxf(m, __shfl_xor_sync(0xffffffffu, m, o));
            if (lane == 0) red[wrp] = m;
            __syncthreads();
            float gm = fmaxf(fmaxf(red[half * 4 + 0], red[half * 4 + 1]),
                             fmaxf(red[half * 4 + 2], red[half * 4 + 3]));
            float e = expf(v - gm);
            float s = e;
            #pragma unroll
            for (int o = 16; o; o >>= 1)
                s += __shfl_xor_sync(0xffffffffu, s, o);
            if (lane == 0) red[8 + wrp] = s;
            __syncthreads();
            float gs = red[8 + half * 4 + 0] + red[8 + half * 4 + 1] +
                       red[8 + half * 4 + 2] + red[8 + half * 4 + 3];
            out[(size_t)b * (T_ * C_) + (size_t)t * C_ + c] = e / gs;
        }
        __syncthreads();
    }

    // ---- restore parity-0 h to zeros so every launch/replay is identical ----
    if (tid < MB) {
        *(uint4*)&g_hhi[0][b0 + tid][J0h] = make_uint4(0, 0, 0, 0);
        *(uint4*)&g_hlo[0][b0 + tid][J0h] = make_uint4(0, 0, 0, 0);
    }
}

extern "C" void kernel_launch(void* const* d_in, const int* in_sizes, int n_in,
                              void* d_out, int out_size) {
    (void)in_sizes; (void)n_in; (void)out_size;
    const float* x   = (const float*)d_in[0];
    const float* Wih = (const float*)d_in[1];
    const float* Whh = (const float*)d_in[2];
    const float* bih = (const float*)d_in[3];
    const float* bhh = (const float*)d_in[4];
    const float* Wd  = (const float*)d_in[5];
    const float* bd  = (const float*)d_in[6];
    float* out = (float*)d_out;

    cudaFuncSetAttribute(lstm_hmma_kernel,
                         cudaFuncAttributeMaxDynamicSharedMemorySize, SMEM_BYTES);
    lstm_hmma_kernel<<<NCTA, NTHR, SMEM_BYTES>>>(x, Wih, Whh, bih, bhh, Wd, bd, out);
}

// round 13
// speedup vs baseline: 1.8045x; 1.2872x over previous
#include <cuda_runtime.h>
#include <cuda_bf16.h>
#include <cstdint>

// Problem constants
#define B_    256
#define T_    2048
#define F_    64
#define H_    512
#define C_    128

// Partitioning: 64 gate-row chunks (32 rows = 8 h-units) x 2 batch chunks (128) = 128 CTAs
#define NJ    64
#define NCTA  128
#define NTHR  256
#define JTH   8       // h-units per CTA
#define NROW  32      // gate rows per CTA
#define MB    128     // batches per CTA

// SMEM byte offsets
// A panels: 8 warps x 2 bufs x (hi 2KB + lo 2KB) = 65536
#define OFF_A     0
#define OFF_WF    65536                   // weight frags: 36*4*32*16 = 73728
#define OFF_HN    139264                  // 8 warps x 8jj x 16 batches f32 = 4096
#define OFF_BSUM  143360                  // 32 f32
#define OFF_BD    143488                  // 128 f32
#define OFF_RED   144000                  // 16 f32
#define SMEM_BYTES 144064

// ---------------- device globals (static scratch; zero-initialized) ---------
__device__ __nv_bfloat16 g_hhi[2][B_][H_];   // h hi, double buffered
__device__ __nv_bfloat16 g_hlo[2][B_][H_];   // h lo
__device__ float g_part[2][NJ][B_][C_];      // decoder partial logits
__device__ unsigned int g_count = 0;
__device__ volatile unsigned int g_sense = 0;

__device__ __forceinline__ float sigm(float x) { return 1.0f / (1.0f + expf(-x)); }
__device__ __forceinline__ uint32_t sw128(uint32_t off) { return off ^ ((off >> 3) & 0x70); }

__device__ __forceinline__ void pack_hilo(float f0, float f1, uint32_t& hi, uint32_t& lo) {
    __nv_bfloat16 h0 = __float2bfloat16(f0), h1 = __float2bfloat16(f1);
    float r0 = f0 - __bfloat162float(h0), r1 = f1 - __bfloat162float(h1);
    __nv_bfloat16 l0 = __float2bfloat16(r0), l1 = __float2bfloat16(r1);
    hi = (uint32_t)__bfloat16_as_ushort(h0) | ((uint32_t)__bfloat16_as_ushort(h1) << 16);
    lo = (uint32_t)__bfloat16_as_ushort(l0) | ((uint32_t)__bfloat16_as_ushort(l1) << 16);
}

#define LDMX4(r0,r1,r2,r3,addr) \
    asm volatile("ldmatrix.sync.aligned.m8n8.x4.shared.b16 {%0,%1,%2,%3}, [%4];" \
                 : "=r"(r0),"=r"(r1),"=r"(r2),"=r"(r3) : "r"(addr))

#define MMA16816(d,a0,a1,a2,a3,b0,b1) \
    asm volatile("mma.sync.aligned.m16n8k16.row.col.f32.bf16.bf16.f32 " \
                 "{%0,%1,%2,%3}, {%4,%5,%6,%7}, {%8,%9}, {%0,%1,%2,%3};" \
                 : "+f"(d[0]),"+f"(d[1]),"+f"(d[2]),"+f"(d[3]) \
                 : "r"(a0),"r"(a1),"r"(a2),"r"(a3), "r"(b0),"r"(b1))

__global__ void __launch_bounds__(NTHR, 1) lstm_hmma_kernel(
    const float* __restrict__ X,    // [B, T, F]
    const float* __restrict__ Wih,  // [4H, F]
    const float* __restrict__ Whh,  // [4H, H]
    const float* __restrict__ bih,  // [4H]
    const float* __restrict__ bhh,  // [4H]
    const float* __restrict__ Wd,   // [C, H]
    const float* __restrict__ bd,   // [C]
    float* __restrict__ out)        // [B, T*C]
{
    extern __shared__ char smc[];
    const uint32_t smb = (uint32_t)__cvta_generic_to_shared(smc);
    uint4*  wfrag = (uint4*)(smc + OFF_WF);   // [36][4][32] {bhi0,bhi1,blo0,blo1}
    float*  bsum  = (float*)(smc + OFF_BSUM); // [32]
    float*  bds   = (float*)(smc + OFF_BD);   // [128]
    float*  red   = (float*)(smc + OFF_RED);  // [16]

    const int tid  = threadIdx.x;
    const int cta  = blockIdx.x;
    const int jb   = cta >> 1;           // gate-row chunk 0..63
    const int bb   = cta & 1;            // batch chunk 0..1
    const int J0h  = jb * JTH;
    const int b0   = bb * MB;
    const int wrp  = tid >> 5;           // warp id 0..7 = m-tile
    const int lane = tid & 31;
    const int rloc = lane >> 1;          // warp-local staging row 0..15
    const int seg  = lane & 1;           // k half (32 elems)

    // ---- one-time init: weight fragments (bf16 hi/lo, mma fragment order) ----
    for (int idx = tid; idx < 36 * 4 * 32; idx += NTHR) {
        int ks = idx >> 7, rem = idx & 127;
        int nt = rem >> 5, l = rem & 31;
        int n = nt * 8 + (l >> 2);                 // gate row 0..31
        int jj = n >> 2, g = n & 3;
        int grow = g * H_ + J0h + jj;              // PyTorch gate order i,f,g,o
        int kA = ks * 16 + (l & 3) * 2;
        float w[4];
        #pragma unroll
        for (int e = 0; e < 4; ++e) {
            int k = kA + (e & 1) + (e >> 1) * 8;
            w[e] = (k < F_) ? Wih[(size_t)grow * F_ + k]
                            : Whh[(size_t)grow * H_ + (k - F_)];
        }
        uint32_t h0, l0, h1, l1;
        pack_hilo(w[0], w[1], h0, l0);
        pack_hilo(w[2], w[3], h1, l1);
        wfrag[idx] = make_uint4(h0, h1, l0, l1);
    }
    if (tid < NROW) {
        int jj = tid >> 2, g = tid & 3;
        bsum[tid] = bih[g * H_ + J0h + jj] + bhh[g * H_ + J0h + jj];
    }
    if (tid < C_) bds[tid] = bd[tid];

    // decoder weights in registers: lane covers c = lane*4 .. +3 for all 8 kk
    float wdr[8][4];
    {
        int c0 = lane * 4;
        #pragma unroll
        for (int kk = 0; kk < JTH; ++kk)
            #pragma unroll
            for (int j = 0; j < 4; ++j)
                wdr[kk][j] = Wd[(size_t)(c0 + j) * H_ + J0h + kk];
    }
    __syncthreads();

    // bias registers for this thread's 4 jj values
    const int jbit = (lane >> 1) & 1;
    float bi[4], bf[4], bg[4], bo[4];
    #pragma unroll
    for (int nt = 0; nt < 4; ++nt) {
        int jj = 2 * nt + jbit;
        bi[nt] = bsum[jj * 4 + 0]; bf[nt] = bsum[jj * 4 + 1];
        bg[nt] = bsum[jj * 4 + 2]; bo[nt] = bsum[jj * 4 + 3];
    }

    float cst[4] = {0.f, 0.f, 0.f, 0.f};
    const int mloc = (lane >> 2) + ((lane & 1) << 3);   // warp-local batch 0..15
    float* hnw = (float*)(smc + OFF_HN) + wrp * 128;    // [8 jj][16]

    // per-warp A buffers
    const uint32_t awarp = smb + OFF_A + wrp * 8192;    // +cur*4096; lo plane +2048
    // precomputed swizzled lane offsets
    uint32_t swst[4], swld[4];
    #pragma unroll
    for (int j = 0; j < 4; ++j)
        swst[j] = sw128((uint32_t)(rloc * 128 + seg * 64 + j * 16));
    #pragma unroll
    for (int ks = 0; ks < 4; ++ks)
        swld[ks] = sw128((uint32_t)((lane & 15) * 128 + ks * 32 + (lane >> 4) * 16));

    const int myb = b0 + wrp * 16 + rloc;               // this lane's staging batch
    uint4 hr[8];                                        // prefetch regs (hi0..3, lo4..7)
    int cur = 0;

    // ---- preloop: stage x(t=0) into buf0; prefetch h panel 1 ----
    {
        const uint4* xp = (const uint4*)(X + ((size_t)myb * T_) * F_ + seg * 32);
        uint4 xf[8];
        #pragma unroll
        for (int i = 0; i < 8; ++i) xf[i] = __ldcg(xp + i);
        #pragma unroll
        for (int j = 0; j < 4; ++j) {
            float4 fa = *(float4*)&xf[2 * j], fb = *(float4*)&xf[2 * j + 1];
            uint32_t h0,l0,h1,l1,h2,l2,h3,l3;
            pack_hilo(fa.x, fa.y, h0, l0); pack_hilo(fa.z, fa.w, h1, l1);
            pack_hilo(fb.x, fb.y, h2, l2); pack_hilo(fb.z, fb.w, h3, l3);
            asm volatile("st.shared.v4.b32 [%0], {%1,%2,%3,%4};"
                         :: "r"(awarp + swst[j]), "r"(h0),"r"(h1),"r"(h2),"r"(h3));
            asm volatile("st.shared.v4.b32 [%0], {%1,%2,%3,%4};"
                         :: "r"(awarp + 2048 + swst[j]), "r"(l0),"r"(l1),"r"(l2),"r"(l3));
        }
        #pragma unroll
        for (int j = 0; j < 4; ++j) {
            hr[j]     = __ldcg((const uint4*)&g_hhi[0][myb][seg * 32 + j * 8]);
            hr[4 + j] = __ldcg((const uint4*)&g_hlo[0][myb][seg * 32 + j * 8]);
        }
    }
    __syncthreads();

    for (int t = 0; t < T_; ++t) {
        const int par = t & 1;

        float acc[4][4];
        #pragma unroll
        for (int nt = 0; nt < 4; ++nt)
            #pragma unroll
            for (int i = 0; i < 4; ++i) acc[nt][i] = 0.f;

        // ---- gates GEMM: 9 panels of K=64, fully warp-local ----
        #pragma unroll 1
        for (int p = 0; p < 9; ++p) {
            const uint32_t bufc = awarp + cur * 4096;
            const uint32_t bufn = awarp + (cur ^ 1) * 4096;
            __syncwarp();          // prior panel's ldmatrix reads of bufn done
            if (p < 8) {
                #pragma unroll
                for (int j = 0; j < 4; ++j) {
                    uint4 h = hr[j], l = hr[4 + j];
                    asm volatile("st.shared.v4.b32 [%0], {%1,%2,%3,%4};"
                                 :: "r"(bufn + swst[j]), "r"(h.x),"r"(h.y),"r"(h.z),"r"(h.w));
                    asm volatile("st.shared.v4.b32 [%0], {%1,%2,%3,%4};"
                                 :: "r"(bufn + 2048 + swst[j]), "r"(l.x),"r"(l.y),"r"(l.z),"r"(l.w));
                }
            } else if (t + 1 < T_) {
                #pragma unroll
                for (int j = 0; j < 4; ++j) {
                    float4 fa = *(float4*)&hr[2 * j], fb = *(float4*)&hr[2 * j + 1];
                    uint32_t h0,l0,h1,l1,h2,l2,h3,l3;
                    pack_hilo(fa.x, fa.y, h0, l0); pack_hilo(fa.z, fa.w, h1, l1);
                    pack_hilo(fb.x, fb.y, h2, l2); pack_hilo(fb.z, fb.w, h3, l3);
                    asm volatile("st.shared.v4.b32 [%0], {%1,%2,%3,%4};"
                                 :: "r"(bufn + swst[j]), "r"(h0),"r"(h1),"r"(h2),"r"(h3));
                    asm volatile("st.shared.v4.b32 [%0], {%1,%2,%3,%4};"
                                 :: "r"(bufn + 2048 + swst[j]), "r"(l0),"r"(l1),"r"(l2),"r"(l3));
                }
            }
            __syncwarp();          // bufn visible to whole warp

            if (p <= 6) {          // prefetch h panel p+2 (h-units (p+1)*64..)
                int kb = (p + 1) * 64 + seg * 32;
                #pragma unroll
                for (int j = 0; j < 4; ++j) {
                    hr[j]     = __ldcg((const uint4*)&g_hhi[par][myb][kb + j * 8]);
                    hr[4 + j] = __ldcg((const uint4*)&g_hlo[par][myb][kb + j * 8]);
                }
            } else if (p == 7 && t + 1 < T_) {   // prefetch next step's x (fp32)
                const uint4* xp = (const uint4*)(X + ((size_t)myb * T_ + (t + 1)) * F_ + seg * 32);
                #pragma unroll
                for (int i = 0; i < 8; ++i) hr[i] = __ldcg(xp + i);
            }

            // compute panel p from bufc
            #pragma unroll
            for (int ks = 0; ks < 4; ++ks) {
                uint32_t ah0, ah1, ah2, ah3, al0, al1, al2, al3;
                LDMX4(ah0, ah1, ah2, ah3, bufc + swld[ks]);
                LDMX4(al0, al1, al2, al3, bufc + 2048 + swld[ks]);
                const uint4* wf = &wfrag[((p * 4 + ks) * 4) * 32 + lane];
                #pragma unroll
                for (int nt = 0; nt < 4; ++nt) {
                    uint4 b = wf[nt * 32];
                    MMA16816(acc[nt], ah0, ah1, ah2, ah3, b.x, b.y);
                    MMA16816(acc[nt], al0, al1, al2, al3, b.x, b.y);
                    MMA16816(acc[nt], ah0, ah1, ah2, ah3, b.z, b.w);
                }
            }
            cur ^= 1;
        }

        // ---- cell update: reassemble quads via lane-pair shuffles (warp-local) ----
        {
            const int odd = lane & 1;
            #pragma unroll
            for (int nt = 0; nt < 4; ++nt) {
                float t0 = __shfl_xor_sync(0xffffffffu, acc[nt][0], 1);
                float t1 = __shfl_xor_sync(0xffffffffu, acc[nt][1], 1);
                float t2 = __shfl_xor_sync(0xffffffffu, acc[nt][2], 1);
                float t3 = __shfl_xor_sync(0xffffffffu, acc[nt][3], 1);
                float pi = odd ? t2 : acc[nt][0];
                float pf = odd ? t3 : acc[nt][1];
                float pg = odd ? acc[nt][2] : t0;
                float po = odd ? acc[nt][3] : t1;
                pi += bi[nt]; pf += bf[nt]; pg += bg[nt]; po += bo[nt];
                float iv = sigm(pi), fv = sigm(pf), gv = tanhf(pg), ov = sigm(po);
                float cn = fv * cst[nt] + iv * gv;
                cst[nt] = cn;
                hnw[(2 * nt + jbit) * 16 + mloc] = ov * tanhf(cn);
            }
        }
        __syncwarp();

        // ---- write h hi/lo to global (next parity), warp-local ----
        {
            int half = seg;                       // 4 h-units per lane
            uint32_t ph[2], pl[2];
            float f0 = hnw[(half * 4 + 0) * 16 + rloc];
            float f1 = hnw[(half * 4 + 1) * 16 + rloc];
            float f2 = hnw[(half * 4 + 2) * 16 + rloc];
            float f3 = hnw[(half * 4 + 3) * 16 + rloc];
            pack_hilo(f0, f1, ph[0], pl[0]);
            pack_hilo(f2, f3, ph[1], pl[1]);
            *(uint2*)&g_hhi[par ^ 1][myb][J0h + half * 4] = make_uint2(ph[0], ph[1]);
            *(uint2*)&g_hlo[par ^ 1][myb][J0h + half * 4] = make_uint2(pl[0], pl[1]);
        }

        // ---- decoder partials for this warp's 16 batches (relu fused) ----
        {
            #pragma unroll 4
            for (int bl = 0; bl < 16; ++bl) {
                float hv[8];
                #pragma unroll
                for (int kk = 0; kk < JTH; ++kk)
                    hv[kk] = fmaxf(hnw[kk * 16 + bl], 0.f);
                float a0 = 0.f, a1 = 0.f, a2 = 0.f, a3 = 0.f;
                #pragma unroll
                for (int kk = 0; kk < JTH; ++kk) {
                    a0 += wdr[kk][0] * hv[kk]; a1 += wdr[kk][1] * hv[kk];
                    a2 += wdr[kk][2] * hv[kk]; a3 += wdr[kk][3] * hv[kk];
                }
                *(float4*)&g_part[par][jb][b0 + wrp * 16 + bl][lane * 4] =
                    make_float4(a0, a1, a2, a3);
            }
        }

        // ---- grid-wide sync (sense-reversing) ----
        {
            unsigned target = (unsigned)((t & 1) ^ 1);
            __syncthreads();
            if (tid == 0) {
                __threadfence();
                unsigned v = atomicAdd(&g_count, 1u);
                if (v == NCTA - 1) {
                    g_count = 0;
                    __threadfence();
                    g_sense = target;
                } else {
                    while (g_sense != target) { __nanosleep(64); }
                }
                __threadfence();
            }
            __syncthreads();
        }

        // ---- prefetch next step's h panel 1 (now published) ----
        if (t + 1 < T_) {
            #pragma unroll
            for (int j = 0; j < 4; ++j) {
                hr[j]     = __ldcg((const uint4*)&g_hhi[par ^ 1][myb][seg * 32 + j * 8]);
                hr[4 + j] = __ldcg((const uint4*)&g_hlo[par ^ 1][myb][seg * 32 + j * 8]);
            }
        }

        // ---- phase 4: reduce partials + softmax + write out (2 batches/CTA) ----
        {
            const int half = tid >> 7, c = tid & 127;
            const int b = cta * 2 + half;
            float v = bds[c];
            #pragma unroll 8
            for (int j2 = 0; j2 < NJ; ++j2)
                v += __ldcg(&g_part[par][j2][b][c]);
            float m = v;
            #pragma unroll
            for (int o = 16; o; o >>= 1)
                m = fmaxf(m, __shfl_xor_sync(0xffffffffu, m, o));
            if (lane == 0) red[wrp] = m;
            __syncthreads();
            float gm = fmaxf(fmaxf(red[half * 4 + 0], red[half * 4 + 1]),
                             fmaxf(red[half * 4 + 2], red[half * 4 + 3]));
            float e = expf(v - gm);
            float s = e;
            #pragma unroll
            for (int o = 16; o; o >>= 1)
                s += __shfl_xor_sync(0xffffffffu, s, o);
            if (lane == 0) red[8 + wrp] = s;
            __syncthreads();
            float gs = red[8 + half * 4 + 0] + red[8 + half * 4 + 1] +
                       red[8 + half * 4 + 2] + red[8 + half * 4 + 3];
            out[(size_t)b * (T_ * C_) + (size_t)t * C_ + c] = e / gs;
        }
    }

    // ---- restore parity-0 h to zeros so every launch/replay is identical ----
    if (tid < MB) {
        *(uint4*)&g_hhi[0][b0 + tid][J0h] = make_uint4(0, 0, 0, 0);
    } else {
        *(uint4*)&g_hlo[0][b0 + (tid - MB)][J0h] = make_uint4(0, 0, 0, 0);
    }
}

extern "C" void kernel_launch(void* const* d_in, const int* in_sizes, int n_in,
                              void* d_out, int out_size) {
    (void)in_sizes; (void)n_in; (void)out_size;
    const float* x   = (const float*)d_in[0];
    const float* Wih = (const float*)d_in[1];
    const float* Whh = (const float*)d_in[2];
    const float* bih = (const float*)d_in[3];
    const float* bhh = (const float*)d_in[4];
    const float* Wd  = (const float*)d_in[5];
    const float* bd  = (const float*)d_in[6];
    float* out = (float*)d_out;

    cudaFuncSetAttribute(lstm_hmma_kernel,
                         cudaFuncAttributeMaxDynamicSharedMemorySize, SMEM_BYTES);
    lstm_hmma_kernel<<<NCTA, NTHR, SMEM_BYTES>>>(x, Wih, Whh, bih, bhh, Wd, bd, out);
}